// round 3
// baseline (speedup 1.0000x reference)
#include <cuda_runtime.h>
#include <cuda_bf16.h>

// Problem constants (fixed by the dataset)
#define BB 4
#define NN 4096
#define FF 512
#define HA 128
#define HV 32

typedef unsigned long long u64;

// ---------------- f32x2 packed-FMA helpers (Blackwell dual fp32 path) --------
__device__ __forceinline__ u64 pack2(float x, float y) {
    u64 r;
    asm("mov.b64 %0, {%1, %2};" : "=l"(r) : "f"(x), "f"(y));
    return r;
}
__device__ __forceinline__ u64 ffma2(u64 a, u64 b, u64 c) {
    u64 d;
    asm("fma.rn.f32x2 %0, %1, %2, %3;" : "=l"(d) : "l"(a), "l"(b), "l"(c));
    return d;
}
__device__ __forceinline__ float2 unpack2(u64 v) {
    float2 r;
    asm("mov.b64 {%0, %1}, %2;" : "=f"(r.x), "=f"(r.y) : "l"(v));
    return r;
}

// ---------------- scratch (no cudaMalloc allowed) ----------------------------
__device__ float g_hn[(size_t)BB * NN * HA];   // 8 MB: normalized actor features
__device__ float g_gen[BB];                    // gen feature (G=1)
__device__ float g_critpart[BB * 512];         // per-block critic partial sums

// ---------------- kernel 0: gen = leaky_relu(gen_number*W_gen + b_gen) -------
__global__ void gen_kernel(const float* __restrict__ gen_number,
                           const float* __restrict__ W_gen,
                           const float* __restrict__ b_gen) {
    int b = threadIdx.x;
    if (b < BB) {
        float z = gen_number[b] * W_gen[0] + b_gen[0];
        g_gen[b] = z > 0.0f ? z : 0.01f * z;
    }
}

// ---------------- kernel 1: fused h-GEMM + normalize + critic ----------------
// One block = 8 rows of feats. 128 threads.
// Thread j computes h[r][j] for 8 rows (K=512 over obs + gen term), then a
// cross-thread reduction gives the row norm; hn is written to g_hn.
// Critic: threads split as (j2 = tid%32 output unit, kg = tid/32 K-chunk).
__global__ void __launch_bounds__(128)
fused_feat_kernel(const float* __restrict__ obs,
                  const float* __restrict__ W_act,
                  const float* __restrict__ b_act,
                  const float* __restrict__ W_v1,
                  const float* __restrict__ b_v1,
                  const float* __restrict__ W_v2) {
    __shared__ float s_obs[8][FF];
    __shared__ float s_n[8][4];
    __shared__ float s_v[4][8][HV];

    const int tid = threadIdx.x;
    const int blk = blockIdx.x;
    const int g0  = blk * 8;          // first global row of this block
    const int b   = g0 >> 12;         // /4096

    // load 8 obs rows (coalesced float4)
    {
        const float4* src = (const float4*)(obs + (size_t)g0 * FF);
        float4* dst = (float4*)&s_obs[0][0];
        #pragma unroll
        for (int i = tid; i < 8 * FF / 4; i += 128) dst[i] = src[i];
    }
    __syncthreads();

    const float gen = g_gen[b];

    // ---- actor hidden: h[r][j] = sum_k obs[r][k]*W_act[k][j] + gen*W_act[512][j] + b_act[j]
    const int j = tid;
    u64 acc[8];
    #pragma unroll
    for (int r = 0; r < 8; r++) acc[r] = 0ull;

    #pragma unroll 4
    for (int k = 0; k < FF; k += 2) {
        float w0 = W_act[(size_t)k * HA + j];
        float w1 = W_act[(size_t)(k + 1) * HA + j];
        u64 w2 = pack2(w0, w1);
        #pragma unroll
        for (int r = 0; r < 8; r++) {
            u64 o2 = *(const u64*)&s_obs[r][k];
            acc[r] = ffma2(o2, w2, acc[r]);
        }
    }

    float h[8];
    {
        const float wg = W_act[(size_t)FF * HA + j];
        const float ba = b_act[j];
        #pragma unroll
        for (int r = 0; r < 8; r++) {
            float2 f = unpack2(acc[r]);
            h[r] = f.x + f.y + gen * wg + ba;
        }
    }

    // ---- row norms: reduce h^2 across the 128 threads
    const int lane = tid & 31, wrp = tid >> 5;
    #pragma unroll
    for (int r = 0; r < 8; r++) {
        float s = h[r] * h[r];
        #pragma unroll
        for (int o = 16; o > 0; o >>= 1) s += __shfl_xor_sync(0xffffffffu, s, o);
        if (lane == 0) s_n[r][wrp] = s;
    }
    __syncthreads();

    #pragma unroll
    for (int r = 0; r < 8; r++) {
        float ss  = s_n[r][0] + s_n[r][1] + s_n[r][2] + s_n[r][3];
        float nrm = fmaxf(sqrtf(ss), 1e-8f);
        g_hn[(size_t)(g0 + r) * HA + j] = h[r] / nrm;
    }

    // ---- critic: v1 = relu(feats@W_v1 + b_v1); v = v1@W_v2 (b_v2 folded later)
    const int j2 = tid & 31;
    const int kg = tid >> 5;
    const int k0 = kg * 128;
    u64 p[8];
    #pragma unroll
    for (int r = 0; r < 8; r++) p[r] = 0ull;

    #pragma unroll 4
    for (int k = k0; k < k0 + 128; k += 2) {
        u64 w2 = pack2(W_v1[(size_t)k * HV + j2], W_v1[(size_t)(k + 1) * HV + j2]);
        #pragma unroll
        for (int r = 0; r < 8; r++) {
            u64 o2 = *(const u64*)&s_obs[r][k];
            p[r] = ffma2(o2, w2, p[r]);
        }
    }
    #pragma unroll
    for (int r = 0; r < 8; r++) {
        float2 f = unpack2(p[r]);
        s_v[kg][r][j2] = f.x + f.y;
    }
    __syncthreads();

    if (tid < 32) {
        const float genw = gen * W_v1[(size_t)FF * HV + tid] + b_v1[tid];
        const float wv2  = W_v2[tid];
        float bsum = 0.0f;
        #pragma unroll
        for (int r = 0; r < 8; r++) {
            float v1 = s_v[0][r][tid] + s_v[1][r][tid] + s_v[2][r][tid] + s_v[3][r][tid] + genw;
            v1 = fmaxf(v1, 0.0f);
            float t = v1 * wv2;
            #pragma unroll
            for (int o = 16; o > 0; o >>= 1) t += __shfl_xor_sync(0xffffffffu, t, o);
            bsum += t;
        }
        if (tid == 0) g_critpart[blk] = bsum;
    }
}

// ---------------- kernel 2: actor = -hn @ hn^T  (symmetric, upper tiles) -----
// 128x128 tile per block, 256 threads, 8x8 micro-tile per thread
// (m contiguous ty*8..+7, n strided tx+16*jn for conflict-free smem reads).
// Full K=128 staged in smem with stride-130 padding.
#define SSTR 130

__global__ void __launch_bounds__(256, 1)
actor_gemm(float* __restrict__ out) {
    extern __shared__ float sm[];
    float* As = sm;                 // 128 x SSTR
    float* Bs = sm + 128 * SSTR;    // 128 x SSTR

    const int b = blockIdx.y;
    // map linear tile-pair index -> (bi, bj), bi <= bj, 32 tiles per dim
    int bi = 0, rem = blockIdx.x;
    while (rem >= 32 - bi) { rem -= 32 - bi; bi++; }
    const int bj = bi + rem;

    const int tid = threadIdx.x;
    const float* base = g_hn + (size_t)b * NN * HA;

    // fill both tiles (coalesced float4 loads, float2 smem stores)
    #pragma unroll
    for (int idx = tid; idx < 128 * 32; idx += 256) {
        int r  = idx >> 5;
        int kq = (idx & 31) << 2;
        float4 va = *(const float4*)(base + (size_t)(bi * 128 + r) * HA + kq);
        *(float2*)&As[r * SSTR + kq]     = make_float2(va.x, va.y);
        *(float2*)&As[r * SSTR + kq + 2] = make_float2(va.z, va.w);
        float4 vb = *(const float4*)(base + (size_t)(bj * 128 + r) * HA + kq);
        *(float2*)&Bs[r * SSTR + kq]     = make_float2(vb.x, vb.y);
        *(float2*)&Bs[r * SSTR + kq + 2] = make_float2(vb.z, vb.w);
    }
    __syncthreads();

    const int tx = tid & 15, ty = tid >> 4;
    const int mrow = ty * 8;

    u64 acc[4][8];
    #pragma unroll
    for (int i = 0; i < 4; i++)
        #pragma unroll
        for (int jn = 0; jn < 8; jn++) acc[i][jn] = 0ull;

    #pragma unroll 2
    for (int k = 0; k < HA; k++) {
        u64 am[4];
        #pragma unroll
        for (int i = 0; i < 4; i++)
            am[i] = pack2(As[(mrow + 2 * i) * SSTR + k],
                          As[(mrow + 2 * i + 1) * SSTR + k]);
        float bn[8];
        #pragma unroll
        for (int jn = 0; jn < 8; jn++) bn[jn] = Bs[(tx + 16 * jn) * SSTR + k];
        #pragma unroll
        for (int jn = 0; jn < 8; jn++) {
            u64 bb = pack2(bn[jn], bn[jn]);
            #pragma unroll
            for (int i = 0; i < 4; i++) acc[i][jn] = ffma2(am[i], bb, acc[i][jn]);
        }
    }

    float av[8][8];   // [mi][jn], negated result
    #pragma unroll
    for (int i = 0; i < 4; i++)
        #pragma unroll
        for (int jn = 0; jn < 8; jn++) {
            float2 f = unpack2(acc[i][jn]);
            av[2 * i][jn]     = -f.x;
            av[2 * i + 1][jn] = -f.y;
        }

    const size_t NSQ = (size_t)NN * NN;
    float* ob = out + (size_t)b * NSQ;
    const int row0 = bi * 128 + mrow;
    const int col0 = bj * 128 + tx;

    // normal orientation (coalesced across tx)
    #pragma unroll
    for (int mi = 0; mi < 8; mi++) {
        float* p = ob + (size_t)(row0 + mi) * NN + col0;
        #pragma unroll
        for (int jn = 0; jn < 8; jn++) p[16 * jn] = av[mi][jn];
    }

    // mirrored tile (symmetry) for off-diagonal blocks
    if (bi != bj) {
        #pragma unroll
        for (int jn = 0; jn < 8; jn++) {
            int col = col0 + 16 * jn;
            float* p = ob + (size_t)col * NN + row0;
            *(float4*)p       = make_float4(av[0][jn], av[1][jn], av[2][jn], av[3][jn]);
            *(float4*)(p + 4) = make_float4(av[4][jn], av[5][jn], av[6][jn], av[7][jn]);
        }
    }
}

// ---------------- kernel 3: deterministic critic reduction -------------------
__global__ void critic_finish(float* __restrict__ out,
                              const float* __restrict__ b_v2,
                              size_t critic_base) {
    __shared__ float s[512];
    const int b = blockIdx.x, tid = threadIdx.x;
    s[tid] = g_critpart[b * 512 + tid];
    __syncthreads();
    #pragma unroll
    for (int o = 256; o > 0; o >>= 1) {
        if (tid < o) s[tid] += s[tid + o];
        __syncthreads();
    }
    if (tid == 0) out[critic_base + b] = s[0] / (float)NN + b_v2[0];
}

// ---------------- launch ------------------------------------------------------
extern "C" void kernel_launch(void* const* d_in, const int* in_sizes, int n_in,
                              void* d_out, int out_size) {
    const float* obs        = (const float*)d_in[0];
    const float* gen_number = (const float*)d_in[1];
    const float* W_gen      = (const float*)d_in[2];
    const float* b_gen      = (const float*)d_in[3];
    const float* W_act      = (const float*)d_in[4];
    const float* b_act      = (const float*)d_in[5];
    const float* W_v1       = (const float*)d_in[6];
    const float* b_v1       = (const float*)d_in[7];
    const float* W_v2       = (const float*)d_in[8];
    const float* b_v2       = (const float*)d_in[9];
    float* out = (float*)d_out;

    const int smem = 2 * 128 * SSTR * (int)sizeof(float);   // 133,120 B
    cudaFuncSetAttribute(actor_gemm, cudaFuncAttributeMaxDynamicSharedMemorySize, smem);

    gen_kernel<<<1, 32>>>(gen_number, W_gen, b_gen);
    fused_feat_kernel<<<(BB * NN) / 8, 128>>>(obs, W_act, b_act, W_v1, b_v1, W_v2);
    actor_gemm<<<dim3(528, BB), 256, smem>>>(out);
    critic_finish<<<BB, 512>>>(out, b_v2, (size_t)out_size - BB);
}

// round 7
// speedup vs baseline: 1.8655x; 1.8655x over previous
#include <cuda_runtime.h>
#include <cuda_bf16.h>
#include <cstdint>

// Problem constants (fixed by the dataset)
#define BB 4
#define NN 4096
#define FF 512
#define HA 128
#define HV 32

typedef unsigned long long u64;

// ================= f32x2 packed-FMA helpers (feat kernel) ====================
__device__ __forceinline__ u64 pack2(float x, float y) {
    u64 r; asm("mov.b64 %0, {%1, %2};" : "=l"(r) : "f"(x), "f"(y)); return r;
}
__device__ __forceinline__ u64 ffma2(u64 a, u64 b, u64 c) {
    u64 d; asm("fma.rn.f32x2 %0, %1, %2, %3;" : "=l"(d) : "l"(a), "l"(b), "l"(c)); return d;
}
__device__ __forceinline__ float2 unpack2(u64 v) {
    float2 r; asm("mov.b64 {%0, %1}, %2;" : "=f"(r.x), "=f"(r.y) : "l"(v)); return r;
}

// ================= mma.sync / ldmatrix helpers (no arch-'a' gating) ==========
__device__ __forceinline__ uint32_t smem_u32(const void* p) {
    uint32_t a;
    asm("{ .reg .u64 t; cvta.to.shared.u64 t, %1; cvt.u32.u64 %0, t; }"
        : "=r"(a) : "l"(p));
    return a;
}
__device__ __forceinline__ void ldsm4(uint32_t& r0, uint32_t& r1,
                                      uint32_t& r2, uint32_t& r3, uint32_t addr) {
    asm volatile("ldmatrix.sync.aligned.m8n8.x4.shared.b16 {%0,%1,%2,%3}, [%4];"
                 : "=r"(r0), "=r"(r1), "=r"(r2), "=r"(r3) : "r"(addr));
}
__device__ __forceinline__ void mma_bf16(float* c, const uint32_t* a,
                                         uint32_t b0, uint32_t b1) {
    asm volatile(
        "mma.sync.aligned.m16n8k16.row.col.f32.bf16.bf16.f32 "
        "{%0,%1,%2,%3}, {%4,%5,%6,%7}, {%8,%9}, {%0,%1,%2,%3};"
        : "+f"(c[0]), "+f"(c[1]), "+f"(c[2]), "+f"(c[3])
        : "r"(a[0]), "r"(a[1]), "r"(a[2]), "r"(a[3]), "r"(b0), "r"(b1));
}

// ================= scratch (no cudaMalloc allowed) ===========================
__device__ __nv_bfloat16 g_hi[(size_t)BB * NN * HA];   // 4 MB: hn hi-part
__device__ __nv_bfloat16 g_lo[(size_t)BB * NN * HA];   // 4 MB: hn lo-part
__device__ float g_critpart[BB * 512];                 // per-block critic partials

// ================= kernel 1: fused h-GEMM + normalize + critic ===============
__global__ void __launch_bounds__(128)
fused_feat_kernel(const float* __restrict__ obs,
                  const float* __restrict__ gen_number,
                  const float* __restrict__ W_gen,
                  const float* __restrict__ b_gen,
                  const float* __restrict__ W_act,
                  const float* __restrict__ b_act,
                  const float* __restrict__ W_v1,
                  const float* __restrict__ b_v1,
                  const float* __restrict__ W_v2) {
    __shared__ float s_obs[8][FF];
    __shared__ float s_n[8][4];
    __shared__ float s_v[4][8][HV];

    const int tid = threadIdx.x;
    const int blk = blockIdx.x;
    const int g0  = blk * 8;
    const int b   = g0 >> 12;

    {
        const float4* src = (const float4*)(obs + (size_t)g0 * FF);
        float4* dst = (float4*)&s_obs[0][0];
        #pragma unroll
        for (int i = tid; i < 8 * FF / 4; i += 128) dst[i] = src[i];
    }
    __syncthreads();

    float zg = gen_number[b] * W_gen[0] + b_gen[0];
    const float gen = zg > 0.0f ? zg : 0.01f * zg;

    // ---- actor hidden
    const int j = tid;
    u64 acc[8];
    #pragma unroll
    for (int r = 0; r < 8; r++) acc[r] = 0ull;

    #pragma unroll 4
    for (int k = 0; k < FF; k += 2) {
        u64 w2 = pack2(W_act[(size_t)k * HA + j], W_act[(size_t)(k + 1) * HA + j]);
        #pragma unroll
        for (int r = 0; r < 8; r++) {
            u64 o2 = *(const u64*)&s_obs[r][k];
            acc[r] = ffma2(o2, w2, acc[r]);
        }
    }

    float h[8];
    {
        const float wg = W_act[(size_t)FF * HA + j];
        const float ba = b_act[j];
        #pragma unroll
        for (int r = 0; r < 8; r++) {
            float2 f = unpack2(acc[r]);
            h[r] = f.x + f.y + gen * wg + ba;
        }
    }

    const int lane = tid & 31, wrp = tid >> 5;
    #pragma unroll
    for (int r = 0; r < 8; r++) {
        float s = h[r] * h[r];
        #pragma unroll
        for (int o = 16; o > 0; o >>= 1) s += __shfl_xor_sync(0xffffffffu, s, o);
        if (lane == 0) s_n[r][wrp] = s;
    }
    __syncthreads();

    #pragma unroll
    for (int r = 0; r < 8; r++) {
        float ss  = s_n[r][0] + s_n[r][1] + s_n[r][2] + s_n[r][3];
        float nrm = fmaxf(sqrtf(ss), 1e-8f);
        float hnv = h[r] / nrm;
        __nv_bfloat16 hi = __float2bfloat16(hnv);
        size_t idx = (size_t)(g0 + r) * HA + j;
        g_hi[idx] = hi;
        g_lo[idx] = __float2bfloat16(hnv - __bfloat162float(hi));
    }

    // ---- critic
    const int j2 = tid & 31;
    const int kg = tid >> 5;
    const int k0 = kg * 128;
    u64 p[8];
    #pragma unroll
    for (int r = 0; r < 8; r++) p[r] = 0ull;

    #pragma unroll 4
    for (int k = k0; k < k0 + 128; k += 2) {
        u64 w2 = pack2(W_v1[(size_t)k * HV + j2], W_v1[(size_t)(k + 1) * HV + j2]);
        #pragma unroll
        for (int r = 0; r < 8; r++) {
            u64 o2 = *(const u64*)&s_obs[r][k];
            p[r] = ffma2(o2, w2, p[r]);
        }
    }
    #pragma unroll
    for (int r = 0; r < 8; r++) {
        float2 f = unpack2(p[r]);
        s_v[kg][r][j2] = f.x + f.y;
    }
    __syncthreads();

    if (tid < 32) {
        const float genw = gen * W_v1[(size_t)FF * HV + tid] + b_v1[tid];
        const float wv2  = W_v2[tid];
        float bsum = 0.0f;
        #pragma unroll
        for (int r = 0; r < 8; r++) {
            float v1 = s_v[0][r][tid] + s_v[1][r][tid] + s_v[2][r][tid] + s_v[3][r][tid] + genw;
            v1 = fmaxf(v1, 0.0f);
            float t = v1 * wv2;
            #pragma unroll
            for (int o = 16; o > 0; o >>= 1) t += __shfl_xor_sync(0xffffffffu, t, o);
            bsum += t;
        }
        if (tid == 0) g_critpart[blk] = bsum;
    }
}

// ================= kernel 2: actor = -hn @ hn^T via mma.sync bf16 ============
// Split-bf16: S = Ah*Bh^T + Ah*Bl^T + Al*Bh^T, fp32 accumulators in registers.
// One CTA = one 128x128 upper-triangular tile (bi<=bj); mirrored store for
// symmetry. 8 warps as 2(m) x 4(n); warp tile 64x32 via m16n8k16.
// smem tiles: 128 rows x 136 bf16 (272 B row stride -> conflict-free ldmatrix).
#define TPITCH 272                       // bytes per smem tile row
#define TBYTES (128 * TPITCH)            // 34816 B per tile

__global__ void __launch_bounds__(256, 1)
actor_gemm_mma(float* __restrict__ out) {
    extern __shared__ char sm[];

    const int tid  = threadIdx.x;
    const int wid  = tid >> 5, lane = tid & 31;

    // map linear tile-pair index -> (bi, bj), bi <= bj
    const int b = blockIdx.y;
    int bi = 0, rem = blockIdx.x;
    while (rem >= 32 - bi) { rem -= 32 - bi; bi++; }
    const int bj = bi + rem;

    // ---- stage 4 operand tiles: t0=Ah(bi), t1=Al(bi), t2=Bh(bj), t3=Bl(bj)
    #pragma unroll
    for (int t = 0; t < 4; t++) {
        const __nv_bfloat16* g = (t & 1) ? g_lo : g_hi;
        const int rb = b * NN + ((t < 2) ? bi : bj) * 128;
        char* tb = sm + t * TBYTES;
        #pragma unroll
        for (int idx = tid; idx < 2048; idx += 256) {
            int r = idx >> 4, cc = idx & 15;     // row, 16B chunk
            uint4 v = *(const uint4*)(g + (size_t)(rb + r) * HA + cc * 8);
            *(uint4*)(tb + r * TPITCH + cc * 16) = v;
        }
    }
    __syncthreads();

    const uint32_t sAh = smem_u32(sm);
    const uint32_t sAl = sAh + TBYTES;
    const uint32_t sBh = sAh + 2 * TBYTES;
    const uint32_t sBl = sAh + 3 * TBYTES;

    const int wm = wid & 1, wn = wid >> 1;       // warp tile: rows wm*64, cols wn*32
    const int m0 = wm * 64, n0 = wn * 32;

    float acc[4][4][4];                          // [m16 chunk][n8 chunk][frag]
    #pragma unroll
    for (int mi = 0; mi < 4; mi++)
        #pragma unroll
        for (int nj = 0; nj < 4; nj++)
            #pragma unroll
            for (int q = 0; q < 4; q++) acc[mi][nj][q] = 0.0f;

    // ldmatrix lane-address components (byte offsets within a tile)
    // A x4: lanes 0-15 -> rows m+0..15 khalf0; lanes 16-31 -> same rows khalf1
    const int a_row  = (lane & 15);
    const int a_half = lane >> 4;
    // B x4: grp g=lane>>3: rows n + (g>>1)*8 + (lane&7), khalf = g&1
    const int b_row  = ((lane >> 4) << 3) + (lane & 7);
    const int b_half = (lane >> 3) & 1;

    #pragma unroll
    for (int term = 0; term < 3; term++) {
        const uint32_t Ab = (term == 2) ? sAl : sAh;
        const uint32_t Bb = (term == 1) ? sBl : sBh;
        const uint32_t aoff = Ab + (m0 + a_row) * TPITCH + a_half * 16;
        const uint32_t boff = Bb + (n0 + b_row) * TPITCH + b_half * 16;

        #pragma unroll
        for (int ks = 0; ks < 8; ks++) {
            const uint32_t kb = ks * 32;
            uint32_t af[4][4];
            #pragma unroll
            for (int mi = 0; mi < 4; mi++)
                ldsm4(af[mi][0], af[mi][1], af[mi][2], af[mi][3],
                      aoff + mi * (16 * TPITCH) + kb);
            uint32_t bf[2][4];
            #pragma unroll
            for (int pr = 0; pr < 2; pr++)
                ldsm4(bf[pr][0], bf[pr][1], bf[pr][2], bf[pr][3],
                      boff + pr * (16 * TPITCH) + kb);
            #pragma unroll
            for (int mi = 0; mi < 4; mi++)
                #pragma unroll
                for (int nj = 0; nj < 4; nj++)
                    mma_bf16(acc[mi][nj], af[mi],
                             bf[nj >> 1][2 * (nj & 1)], bf[nj >> 1][2 * (nj & 1) + 1]);
        }
    }

    // ---- epilogue: negate + direct stores (and mirrored tile for bi != bj)
    const size_t NSQ = (size_t)NN * NN;
    float* ob = out + (size_t)b * NSQ;
    const int rbase = bi * 128 + m0 + (lane >> 2);     // + mi*16 (+8 for c2/c3)
    const int cbase = bj * 128 + n0 + 2 * (lane & 3);  // + nj*8 (+1 for odd)

    #pragma unroll
    for (int mi = 0; mi < 4; mi++) {
        #pragma unroll
        for (int nj = 0; nj < 4; nj++) {
            float v0 = -acc[mi][nj][0], v1 = -acc[mi][nj][1];
            float v2 = -acc[mi][nj][2], v3 = -acc[mi][nj][3];
            const int r0 = rbase + mi * 16;
            const int c0 = cbase + nj * 8;
            *(float2*)(ob + (size_t)r0 * NN + c0)       = make_float2(v0, v1);
            *(float2*)(ob + (size_t)(r0 + 8) * NN + c0) = make_float2(v2, v3);
            if (bi != bj) {
                ob[(size_t)c0 * NN + r0]           = v0;
                ob[(size_t)(c0 + 1) * NN + r0]     = v1;
                ob[(size_t)c0 * NN + r0 + 8]       = v2;
                ob[(size_t)(c0 + 1) * NN + r0 + 8] = v3;
            }
        }
    }
}

// ================= kernel 3: deterministic critic reduction ==================
__global__ void critic_finish(float* __restrict__ out,
                              const float* __restrict__ b_v2,
                              size_t critic_base) {
    __shared__ float s[512];
    const int b = blockIdx.x, tid = threadIdx.x;
    s[tid] = g_critpart[b * 512 + tid];
    __syncthreads();
    #pragma unroll
    for (int o = 256; o > 0; o >>= 1) {
        if (tid < o) s[tid] += s[tid + o];
        __syncthreads();
    }
    if (tid == 0) out[critic_base + b] = s[0] / (float)NN + b_v2[0];
}

// ================= launch =====================================================
extern "C" void kernel_launch(void* const* d_in, const int* in_sizes, int n_in,
                              void* d_out, int out_size) {
    const float* obs        = (const float*)d_in[0];
    const float* gen_number = (const float*)d_in[1];
    const float* W_gen      = (const float*)d_in[2];
    const float* b_gen      = (const float*)d_in[3];
    const float* W_act      = (const float*)d_in[4];
    const float* b_act      = (const float*)d_in[5];
    const float* W_v1       = (const float*)d_in[6];
    const float* b_v1       = (const float*)d_in[7];
    const float* W_v2       = (const float*)d_in[8];
    const float* b_v2       = (const float*)d_in[9];
    float* out = (float*)d_out;

    const int smem = 4 * TBYTES;   // 139,264 B
    cudaFuncSetAttribute(actor_gemm_mma, cudaFuncAttributeMaxDynamicSharedMemorySize, smem);

    fused_feat_kernel<<<(BB * NN) / 8, 128>>>(obs, gen_number, W_gen, b_gen,
                                              W_act, b_act, W_v1, b_v1, W_v2);
    actor_gemm_mma<<<dim3(528, BB), 256, smem>>>(out);
    critic_finish<<<BB, 512>>>(out, b_v2, (size_t)out_size - BB);
}

// round 11
// speedup vs baseline: 2.9271x; 1.5691x over previous
#include <cuda_runtime.h>
#include <cuda_bf16.h>
#include <cstdint>

// Problem constants (fixed by the dataset)
#define BB 4
#define NN 4096
#define FF 512
#define HA 128
#define HV 32
#define NO 160          // HA + HV combined output width of feat GEMM

typedef unsigned long long u64;

// ================= mma.sync / ldmatrix / cp.async helpers ====================
__device__ __forceinline__ uint32_t smem_u32(const void* p) {
    uint32_t a;
    asm("{ .reg .u64 t; cvta.to.shared.u64 t, %1; cvt.u32.u64 %0, t; }"
        : "=r"(a) : "l"(p));
    return a;
}
__device__ __forceinline__ void ldsm4(uint32_t& r0, uint32_t& r1,
                                      uint32_t& r2, uint32_t& r3, uint32_t addr) {
    asm volatile("ldmatrix.sync.aligned.m8n8.x4.shared.b16 {%0,%1,%2,%3}, [%4];"
                 : "=r"(r0), "=r"(r1), "=r"(r2), "=r"(r3) : "r"(addr));
}
__device__ __forceinline__ void mma_bf16(float* c, const uint32_t* a,
                                         uint32_t b0, uint32_t b1) {
    asm volatile(
        "mma.sync.aligned.m16n8k16.row.col.f32.bf16.bf16.f32 "
        "{%0,%1,%2,%3}, {%4,%5,%6,%7}, {%8,%9}, {%0,%1,%2,%3};"
        : "+f"(c[0]), "+f"(c[1]), "+f"(c[2]), "+f"(c[3])
        : "r"(a[0]), "r"(a[1]), "r"(a[2]), "r"(a[3]), "r"(b0), "r"(b1));
}
__device__ __forceinline__ void cp16(uint32_t dst, const void* src) {
    asm volatile("cp.async.cg.shared.global [%0], [%1], 16;"
                 :: "r"(dst), "l"(src) : "memory");
}
#define CP_COMMIT asm volatile("cp.async.commit_group;" ::: "memory")
#define CP_WAIT0  asm volatile("cp.async.wait_group 0;" ::: "memory")
#define CP_WAIT1  asm volatile("cp.async.wait_group 1;" ::: "memory")

// ================= scratch (no cudaMalloc allowed) ===========================
__device__ __nv_bfloat16 g_hi[(size_t)BB * NN * HA];    // 4 MB: hn hi-part
__device__ __nv_bfloat16 g_lo[(size_t)BB * NN * HA];    // 4 MB: hn lo-part
__device__ __nv_bfloat16 g_wt_hi[NO * FF];              // W^T hi  [160][512]
__device__ __nv_bfloat16 g_wt_lo[NO * FF];              // W^T lo
__device__ float g_critpart[BB * 32];                   // per row-block critic partials

// ================= kernel 0: split/transpose weights =========================
// Wt[n][k]: n<128 -> W_act[k][n], n>=128 -> W_v1[k][n-128]; hi/lo bf16 split.
__global__ void __launch_bounds__(256)
wsplit_kernel(const float* __restrict__ W_act, const float* __restrict__ W_v1) {
    int idx = blockIdx.x * 256 + threadIdx.x;
    if (idx >= NO * FF) return;
    int n = idx >> 9, k = idx & 511;
    float w = (n < HA) ? W_act[(size_t)k * HA + n] : W_v1[(size_t)k * HV + (n - HA)];
    __nv_bfloat16 hi = __float2bfloat16(w);
    g_wt_hi[idx] = hi;
    g_wt_lo[idx] = __float2bfloat16(w - __bfloat162float(hi));
}

// ================= kernel 1: feat GEMM (mma.sync) + normalize + critic =======
// One CTA: 128 rows x 160 cols, K=512 in 4 chunks of 128. Split-bf16 3-term.
// smem layout (dynamic): Whi(43520) Wlo(43520) Ahi(34816) Alo(34816) = 156672 B
// (aliased by h[128][162] fp32 in the epilogue).
#define FP 272                       // pitch bytes for 128-bf16 rows
#define W_TILE (NO * FP)             // 43520
#define A_TILE (128 * FP)            // 34816
#define FEAT_SMEM (2 * W_TILE + 2 * A_TILE)
#define HP 162                       // h epilogue pitch (floats)

__global__ void __launch_bounds__(256, 1)
feat_kernel(const float* __restrict__ obs,
            const float* __restrict__ gen_number,
            const float* __restrict__ W_gen,
            const float* __restrict__ b_gen,
            const float* __restrict__ W_act,
            const float* __restrict__ b_act,
            const float* __restrict__ W_v1,
            const float* __restrict__ b_v1,
            const float* __restrict__ W_v2) {
    extern __shared__ char sm[];
    __shared__ float sbias[NO];
    __shared__ float snorm[128];
    __shared__ float sv2[HV];
    __shared__ float srowv[128];

    const int tid = threadIdx.x;
    const int wid = tid >> 5, lane = tid & 31;
    const int g0 = blockIdx.x * 128;          // first global row
    const int b  = blockIdx.x >> 5;           // batch

    const uint32_t sWh = smem_u32(sm);
    const uint32_t sWl = sWh + W_TILE;
    const uint32_t sAh = sWh + 2 * W_TILE;
    const uint32_t sAl = sAh + A_TILE;
    char* pWh = sm;
    char* pWl = sm + W_TILE;
    char* pAh = sm + 2 * W_TILE;
    char* pAl = pAh + A_TILE;

    const int wm = wid & 1, wn = wid >> 1;    // warp tile: rows wm*64, cols wn*40
    const int m0 = wm * 64, n0 = wn * 40;

    float acc[4][5][4];
    #pragma unroll
    for (int mi = 0; mi < 4; mi++)
        #pragma unroll
        for (int nj = 0; nj < 5; nj++)
            #pragma unroll
            for (int q = 0; q < 4; q++) acc[mi][nj][q] = 0.0f;

    const int a_row  = lane & 15;
    const int a_half = lane >> 4;
    const int b_row  = ((lane >> 4) << 3) + (lane & 7);
    const int b_half = (lane >> 3) & 1;

    for (int kc = 0; kc < 4; kc++) {
        // stage obs chunk -> split bf16 (128 rows x 128 k)
        #pragma unroll
        for (int it = 0; it < 16; it++) {
            int u = tid + it * 256;            // 4096 float4 units
            int r = u >> 5, c4 = u & 31;
            float4 v = *(const float4*)(obs + (size_t)(g0 + r) * FF + kc * 128 + c4 * 4);
            __nv_bfloat16 h0 = __float2bfloat16(v.x), h1 = __float2bfloat16(v.y);
            __nv_bfloat16 h2 = __float2bfloat16(v.z), h3 = __float2bfloat16(v.w);
            __nv_bfloat162* dh = (__nv_bfloat162*)(pAh + r * FP + c4 * 8);
            dh[0] = __nv_bfloat162(h0, h1);
            dh[1] = __nv_bfloat162(h2, h3);
            __nv_bfloat162* dl = (__nv_bfloat162*)(pAl + r * FP + c4 * 8);
            dl[0] = __nv_bfloat162(__float2bfloat16(v.x - __bfloat162float(h0)),
                                   __float2bfloat16(v.y - __bfloat162float(h1)));
            dl[1] = __nv_bfloat162(__float2bfloat16(v.z - __bfloat162float(h2)),
                                   __float2bfloat16(v.w - __bfloat162float(h3)));
        }
        // stage W chunk (160 rows x 128 k, hi + lo)
        #pragma unroll
        for (int it = 0; it < 10; it++) {
            int u = tid + it * 256;            // 2560 uint4 units
            int n = u >> 4, cc = u & 15;
            *(uint4*)(pWh + n * FP + cc * 16) =
                *(const uint4*)(g_wt_hi + (size_t)n * FF + kc * 128 + cc * 8);
            *(uint4*)(pWl + n * FP + cc * 16) =
                *(const uint4*)(g_wt_lo + (size_t)n * FF + kc * 128 + cc * 8);
        }
        __syncthreads();

        #pragma unroll
        for (int term = 0; term < 3; term++) {
            const uint32_t Ab = (term == 2) ? sAl : sAh;
            const uint32_t Wb = (term == 1) ? sWl : sWh;
            const uint32_t aoff = Ab + (m0 + a_row) * FP + a_half * 16;
            const uint32_t boff = Wb + (n0 + b_row) * FP + b_half * 16;
            #pragma unroll
            for (int ks = 0; ks < 8; ks++) {
                const uint32_t kb = ks * 32;
                uint32_t af[4][4];
                #pragma unroll
                for (int mi = 0; mi < 4; mi++)
                    ldsm4(af[mi][0], af[mi][1], af[mi][2], af[mi][3],
                          aoff + mi * (16 * FP) + kb);
                uint32_t bf[3][4];
                #pragma unroll
                for (int pr = 0; pr < 3; pr++)     // rows n0+0/16/32 (over-read ok)
                    ldsm4(bf[pr][0], bf[pr][1], bf[pr][2], bf[pr][3],
                          boff + pr * (16 * FP) + kb);
                #pragma unroll
                for (int mi = 0; mi < 4; mi++)
                    #pragma unroll
                    for (int nj = 0; nj < 5; nj++)
                        mma_bf16(acc[mi][nj], af[mi],
                                 bf[nj >> 1][2 * (nj & 1)], bf[nj >> 1][2 * (nj & 1) + 1]);
            }
        }
        __syncthreads();
    }

    // ---- epilogue: bias row, h to smem, normalize, split-store, critic
    float zg = gen_number[b] * W_gen[0] + b_gen[0];
    const float gen = zg > 0.0f ? zg : 0.01f * zg;
    if (tid < NO) {
        sbias[tid] = (tid < HA)
            ? gen * W_act[(size_t)FF * HA + tid] + b_act[tid]
            : gen * W_v1[(size_t)FF * HV + (tid - HA)] + b_v1[tid - HA];
    }
    if (tid < HV) sv2[tid] = W_v2[tid];

    float* sh = (float*)sm;                    // [128][HP], aliases operand smem
    #pragma unroll
    for (int mi = 0; mi < 4; mi++)
        #pragma unroll
        for (int nj = 0; nj < 5; nj++) {
            int r = m0 + mi * 16 + (lane >> 2);
            int c = n0 + nj * 8 + 2 * (lane & 3);
            sh[r * HP + c]           = acc[mi][nj][0];
            sh[r * HP + c + 1]       = acc[mi][nj][1];
            sh[(r + 8) * HP + c]     = acc[mi][nj][2];
            sh[(r + 8) * HP + c + 1] = acc[mi][nj][3];
        }
    __syncthreads();

    if (tid < 128) {
        const int r = tid;
        float ss = 0.0f;
        #pragma unroll 8
        for (int c = 0; c < HA; c++) {
            float x = sh[r * HP + c] + sbias[c];
            ss += x * x;
        }
        snorm[r] = 1.0f / fmaxf(sqrtf(ss), 1e-8f);
        float vsum = 0.0f;
        #pragma unroll
        for (int j = 0; j < HV; j++) {
            float x = sh[r * HP + HA + j] + sbias[HA + j];
            vsum += fmaxf(x, 0.0f) * sv2[j];
        }
        srowv[r] = vsum;
    }
    __syncthreads();

    // split-bf16 hn store (coalesced)
    #pragma unroll
    for (int it = 0; it < 16; it++) {
        int u = tid + it * 256;                // 4096 groups of 4 cols
        int r = u >> 5, c4 = (u & 31) * 4;
        float rn = snorm[r];
        float x0 = (sh[r * HP + c4 + 0] + sbias[c4 + 0]) * rn;
        float x1 = (sh[r * HP + c4 + 1] + sbias[c4 + 1]) * rn;
        float x2 = (sh[r * HP + c4 + 2] + sbias[c4 + 2]) * rn;
        float x3 = (sh[r * HP + c4 + 3] + sbias[c4 + 3]) * rn;
        __nv_bfloat16 h0 = __float2bfloat16(x0), h1 = __float2bfloat16(x1);
        __nv_bfloat16 h2 = __float2bfloat16(x2), h3 = __float2bfloat16(x3);
        size_t o = (size_t)(g0 + r) * HA + c4;
        *(__nv_bfloat162*)(g_hi + o)     = __nv_bfloat162(h0, h1);
        *(__nv_bfloat162*)(g_hi + o + 2) = __nv_bfloat162(h2, h3);
        *(__nv_bfloat162*)(g_lo + o) =
            __nv_bfloat162(__float2bfloat16(x0 - __bfloat162float(h0)),
                           __float2bfloat16(x1 - __bfloat162float(h1)));
        *(__nv_bfloat162*)(g_lo + o + 2) =
            __nv_bfloat162(__float2bfloat16(x2 - __bfloat162float(h2)),
                           __float2bfloat16(x3 - __bfloat162float(h3)));
    }

    if (tid < 32) {
        float s = srowv[tid] + srowv[tid + 32] + srowv[tid + 64] + srowv[tid + 96];
        #pragma unroll
        for (int o = 16; o > 0; o >>= 1) s += __shfl_xor_sync(0xffffffffu, s, o);
        if (tid == 0) g_critpart[blockIdx.x] = s;
    }
}

// ================= kernel 2: actor = -hn @ hn^T (persistent, pipelined) ======
// 148 persistent CTAs walk contiguous ranges of the 2112 (b, bi<=bj) tile-pairs.
// A-pair (Ah,Al) smem-resident per bi-panel; B-pair double-buffered via cp.async.
#define TPITCH 272
#define TBYTES (128 * TPITCH)            // 34816 per tile
#define PAIRB  (2 * TBYTES)              // hi+lo pair
#define ACTOR_SMEM (PAIRB + 2 * PAIRB)   // A pair + 2 B buffers = 208896
#define NWORK (BB * 528)                 // 2112
#define NCTA 148

__device__ __forceinline__ void issue_pair(char* dst, int b_, int tile, int tid) {
    const size_t rowbase = ((size_t)b_ * NN + (size_t)tile * 128) * HA;
    #pragma unroll
    for (int it = 0; it < 8; it++) {         // 2048 16B units per tile
        int u = tid + it * 256;
        int r = u >> 4, cc = u & 15;
        cp16(smem_u32(dst + r * TPITCH + cc * 16),
             (const char*)(g_hi + rowbase + (size_t)r * HA) + cc * 16);
        cp16(smem_u32(dst + TBYTES + r * TPITCH + cc * 16),
             (const char*)(g_lo + rowbase + (size_t)r * HA) + cc * 16);
    }
}

__global__ void __launch_bounds__(256, 1)
actor_gemm_mma(float* __restrict__ out) {
    extern __shared__ char sm[];
    const int tid = threadIdx.x;
    const int wid = tid >> 5, lane = tid & 31;

    const int start = (int)((long long)blockIdx.x * NWORK / NCTA);
    const int end   = (int)((long long)(blockIdx.x + 1) * NWORK / NCTA);

    // decode start -> (b, bi, bj)
    int b = start / 528;
    int t = start - b * 528;
    int bi = 0;
    while (t >= 32 - bi) { t -= 32 - bi; bi++; }
    int bj = bi + t;

    char* pA  = sm;
    char* pB0 = sm + PAIRB;
    char* pB1 = sm + 2 * PAIRB;

    // prologue: A panel + first B
    issue_pair(pA, b, bi, tid);  CP_COMMIT;
    issue_pair((start & 1) ? pB1 : pB0, b, bj, tid);  CP_COMMIT;
    bool need_A = false;

    const int wm = wid & 1, wn = wid >> 1;
    const int m0 = wm * 64, n0 = wn * 32;
    const int a_row  = lane & 15;
    const int a_half = lane >> 4;
    const int b_row  = ((lane >> 4) << 3) + (lane & 7);
    const int b_half = (lane >> 3) & 1;
    const size_t NSQ = (size_t)NN * NN;

    for (int s = start; s < end; s++) {
        char* pB = (s & 1) ? pB1 : pB0;

        // next work item
        int nb = b, nbi = bi, nbj = bj + 1;
        const bool have_next = (s + 1 < end);
        if (have_next && nbj == 32) {
            nbi++;
            if (nbi == 32) { nb++; nbi = 0; }
            nbj = nbi;
        }
        const bool next_newA = have_next && (nbi != bi || nb != b);

        if (need_A) { issue_pair(pA, b, bi, tid); CP_COMMIT; }
        bool prefetched = false;
        if (have_next) {
            issue_pair(((s + 1) & 1) ? pB1 : pB0, nb, nbj, tid);
            CP_COMMIT;
            prefetched = true;
        }
        if (prefetched) CP_WAIT1; else CP_WAIT0;
        __syncthreads();

        // ---- MMA: 3 split terms x 8 k16 chunks
        const uint32_t sA = smem_u32(pA);
        const uint32_t sB = smem_u32(pB);
        float acc[4][4][4];
        #pragma unroll
        for (int mi = 0; mi < 4; mi++)
            #pragma unroll
            for (int nj = 0; nj < 4; nj++)
                #pragma unroll
                for (int q = 0; q < 4; q++) acc[mi][nj][q] = 0.0f;

        #pragma unroll
        for (int term = 0; term < 3; term++) {
            const uint32_t Ab = sA + ((term == 2) ? TBYTES : 0);
            const uint32_t Bb = sB + ((term == 1) ? TBYTES : 0);
            const uint32_t aoff = Ab + (m0 + a_row) * TPITCH + a_half * 16;
            const uint32_t boff = Bb + (n0 + b_row) * TPITCH + b_half * 16;
            #pragma unroll
            for (int ks = 0; ks < 8; ks++) {
                const uint32_t kb = ks * 32;
                uint32_t af[4][4];
                #pragma unroll
                for (int mi = 0; mi < 4; mi++)
                    ldsm4(af[mi][0], af[mi][1], af[mi][2], af[mi][3],
                          aoff + mi * (16 * TPITCH) + kb);
                uint32_t bf[2][4];
                #pragma unroll
                for (int pr = 0; pr < 2; pr++)
                    ldsm4(bf[pr][0], bf[pr][1], bf[pr][2], bf[pr][3],
                          boff + pr * (16 * TPITCH) + kb);
                #pragma unroll
                for (int mi = 0; mi < 4; mi++)
                    #pragma unroll
                    for (int nj = 0; nj < 4; nj++)
                        mma_bf16(acc[mi][nj], af[mi],
                                 bf[nj >> 1][2 * (nj & 1)], bf[nj >> 1][2 * (nj & 1) + 1]);
            }
        }

        // ---- epilogue: negate + direct stores (+ mirrored tile for bi != bj)
        float* ob = out + (size_t)b * NSQ;
        const int rbase = bi * 128 + m0 + (lane >> 2);
        const int cbase = bj * 128 + n0 + 2 * (lane & 3);
        #pragma unroll
        for (int mi = 0; mi < 4; mi++) {
            #pragma unroll
            for (int nj = 0; nj < 4; nj++) {
                float v0 = -acc[mi][nj][0], v1 = -acc[mi][nj][1];
                float v2 = -acc[mi][nj][2], v3 = -acc[mi][nj][3];
                const int r0 = rbase + mi * 16;
                const int c0 = cbase + nj * 8;
                *(float2*)(ob + (size_t)r0 * NN + c0)       = make_float2(v0, v1);
                *(float2*)(ob + (size_t)(r0 + 8) * NN + c0) = make_float2(v2, v3);
                if (bi != bj) {
                    ob[(size_t)c0 * NN + r0]           = v0;
                    ob[(size_t)(c0 + 1) * NN + r0]     = v1;
                    ob[(size_t)c0 * NN + r0 + 8]       = v2;
                    ob[(size_t)(c0 + 1) * NN + r0 + 8] = v3;
                }
            }
        }
        __syncthreads();

        b = nb; bi = nbi; bj = nbj;
        need_A = next_newA;
    }
}

// ================= kernel 3: deterministic critic reduction ==================
__global__ void critic_finish(float* __restrict__ out,
                              const float* __restrict__ b_v2,
                              size_t critic_base) {
    const int b = blockIdx.x, tid = threadIdx.x;   // 32 threads
    float s = g_critpart[b * 32 + tid];
    #pragma unroll
    for (int o = 16; o > 0; o >>= 1) s += __shfl_xor_sync(0xffffffffu, s, o);
    if (tid == 0) out[critic_base + b] = s / (float)NN + b_v2[0];
}

// ================= launch =====================================================
extern "C" void kernel_launch(void* const* d_in, const int* in_sizes, int n_in,
                              void* d_out, int out_size) {
    const float* obs        = (const float*)d_in[0];
    const float* gen_number = (const float*)d_in[1];
    const float* W_gen      = (const float*)d_in[2];
    const float* b_gen      = (const float*)d_in[3];
    const float* W_act      = (const float*)d_in[4];
    const float* b_act      = (const float*)d_in[5];
    const float* W_v1       = (const float*)d_in[6];
    const float* b_v1       = (const float*)d_in[7];
    const float* W_v2       = (const float*)d_in[8];
    const float* b_v2       = (const float*)d_in[9];
    float* out = (float*)d_out;

    cudaFuncSetAttribute(feat_kernel,
                         cudaFuncAttributeMaxDynamicSharedMemorySize, FEAT_SMEM);
    cudaFuncSetAttribute(actor_gemm_mma,
                         cudaFuncAttributeMaxDynamicSharedMemorySize, ACTOR_SMEM);

    wsplit_kernel<<<(NO * FF + 255) / 256, 256>>>(W_act, W_v1);
    feat_kernel<<<128, 256, FEAT_SMEM>>>(obs, gen_number, W_gen, b_gen,
                                         W_act, b_act, W_v1, b_v1, W_v2);
    actor_gemm_mma<<<NCTA, 256, ACTOR_SMEM>>>(out);
    critic_finish<<<BB, 32>>>(out, b_v2, (size_t)out_size - BB);
}

// round 13
// speedup vs baseline: 3.1372x; 1.0718x over previous
#include <cuda_runtime.h>
#include <cuda_bf16.h>
#include <cstdint>

// Problem constants (fixed by the dataset)
#define BB 4
#define NN 4096
#define FF 512
#define HA 128
#define HV 32
#define NO 160          // HA + HV combined output width of feat GEMM

typedef unsigned long long u64;

// ================= mma.sync / ldmatrix / cp.async helpers ====================
__device__ __forceinline__ uint32_t smem_u32(const void* p) {
    uint32_t a;
    asm("{ .reg .u64 t; cvta.to.shared.u64 t, %1; cvt.u32.u64 %0, t; }"
        : "=r"(a) : "l"(p));
    return a;
}
__device__ __forceinline__ void ldsm4(uint32_t& r0, uint32_t& r1,
                                      uint32_t& r2, uint32_t& r3, uint32_t addr) {
    asm volatile("ldmatrix.sync.aligned.m8n8.x4.shared.b16 {%0,%1,%2,%3}, [%4];"
                 : "=r"(r0), "=r"(r1), "=r"(r2), "=r"(r3) : "r"(addr));
}
__device__ __forceinline__ void mma_bf16(float* c, const uint32_t* a,
                                         uint32_t b0, uint32_t b1) {
    asm volatile(
        "mma.sync.aligned.m16n8k16.row.col.f32.bf16.bf16.f32 "
        "{%0,%1,%2,%3}, {%4,%5,%6,%7}, {%8,%9}, {%0,%1,%2,%3};"
        : "+f"(c[0]), "+f"(c[1]), "+f"(c[2]), "+f"(c[3])
        : "r"(a[0]), "r"(a[1]), "r"(a[2]), "r"(a[3]), "r"(b0), "r"(b1));
}
__device__ __forceinline__ void cp16(uint32_t dst, const void* src) {
    asm volatile("cp.async.cg.shared.global [%0], [%1], 16;"
                 :: "r"(dst), "l"(src) : "memory");
}
#define CP_COMMIT asm volatile("cp.async.commit_group;" ::: "memory")
#define CP_WAIT0  asm volatile("cp.async.wait_group 0;" ::: "memory")
#define CP_WAIT1  asm volatile("cp.async.wait_group 1;" ::: "memory")

// ================= scratch (no cudaMalloc allowed) ===========================
__device__ __nv_bfloat16 g_hi[(size_t)BB * NN * HA];    // 4 MB: hn hi-part
__device__ __nv_bfloat16 g_lo[(size_t)BB * NN * HA];    // 4 MB: hn lo-part
__device__ __nv_bfloat16 g_wt_hi[NO * FF];              // W^T hi  [160][512]
__device__ __nv_bfloat16 g_wt_lo[NO * FF];              // W^T lo
__device__ float g_critpart[BB * 32];                   // per row-block critic partials

// ================= kernel 0: split/transpose weights =========================
__global__ void __launch_bounds__(256)
wsplit_kernel(const float* __restrict__ W_act, const float* __restrict__ W_v1) {
    int idx = blockIdx.x * 256 + threadIdx.x;
    if (idx >= NO * FF) return;
    int n = idx >> 9, k = idx & 511;
    float w = (n < HA) ? W_act[(size_t)k * HA + n] : W_v1[(size_t)k * HV + (n - HA)];
    __nv_bfloat16 hi = __float2bfloat16(w);
    g_wt_hi[idx] = hi;
    g_wt_lo[idx] = __float2bfloat16(w - __bfloat162float(hi));
}

// ================= kernel 1: feat GEMM (mma.sync) + normalize + critic =======
#define FP 272                       // pitch bytes for 128-bf16 rows
#define W_TILE (NO * FP)             // 43520
#define A_TILE (128 * FP)            // 34816
#define FEAT_SMEM (2 * W_TILE + 2 * A_TILE)
#define HP 162                       // h epilogue pitch (floats)

__global__ void __launch_bounds__(256, 1)
feat_kernel(const float* __restrict__ obs,
            const float* __restrict__ gen_number,
            const float* __restrict__ W_gen,
            const float* __restrict__ b_gen,
            const float* __restrict__ W_act,
            const float* __restrict__ b_act,
            const float* __restrict__ W_v1,
            const float* __restrict__ b_v1,
            const float* __restrict__ W_v2) {
    extern __shared__ char sm[];
    __shared__ float sbias[NO];
    __shared__ float snorm[128];
    __shared__ float sv2[HV];
    __shared__ float srowv[128];

    const int tid = threadIdx.x;
    const int wid = tid >> 5, lane = tid & 31;
    const int g0 = blockIdx.x * 128;
    const int b  = blockIdx.x >> 5;

    const uint32_t sWh = smem_u32(sm);
    const uint32_t sWl = sWh + W_TILE;
    const uint32_t sAh = sWh + 2 * W_TILE;
    const uint32_t sAl = sAh + A_TILE;
    char* pWh = sm;
    char* pWl = sm + W_TILE;
    char* pAh = sm + 2 * W_TILE;
    char* pAl = pAh + A_TILE;

    const int wm = wid & 1, wn = wid >> 1;
    const int m0 = wm * 64, n0 = wn * 40;

    float acc[4][5][4];
    #pragma unroll
    for (int mi = 0; mi < 4; mi++)
        #pragma unroll
        for (int nj = 0; nj < 5; nj++)
            #pragma unroll
            for (int q = 0; q < 4; q++) acc[mi][nj][q] = 0.0f;

    const int a_row  = lane & 15;
    const int a_half = lane >> 4;
    const int b_row  = ((lane >> 4) << 3) + (lane & 7);
    const int b_half = (lane >> 3) & 1;

    for (int kc = 0; kc < 4; kc++) {
        #pragma unroll
        for (int it = 0; it < 16; it++) {
            int u = tid + it * 256;
            int r = u >> 5, c4 = u & 31;
            float4 v = *(const float4*)(obs + (size_t)(g0 + r) * FF + kc * 128 + c4 * 4);
            __nv_bfloat16 h0 = __float2bfloat16(v.x), h1 = __float2bfloat16(v.y);
            __nv_bfloat16 h2 = __float2bfloat16(v.z), h3 = __float2bfloat16(v.w);
            __nv_bfloat162* dh = (__nv_bfloat162*)(pAh + r * FP + c4 * 8);
            dh[0] = __nv_bfloat162(h0, h1);
            dh[1] = __nv_bfloat162(h2, h3);
            __nv_bfloat162* dl = (__nv_bfloat162*)(pAl + r * FP + c4 * 8);
            dl[0] = __nv_bfloat162(__float2bfloat16(v.x - __bfloat162float(h0)),
                                   __float2bfloat16(v.y - __bfloat162float(h1)));
            dl[1] = __nv_bfloat162(__float2bfloat16(v.z - __bfloat162float(h2)),
                                   __float2bfloat16(v.w - __bfloat162float(h3)));
        }
        #pragma unroll
        for (int it = 0; it < 10; it++) {
            int u = tid + it * 256;
            int n = u >> 4, cc = u & 15;
            *(uint4*)(pWh + n * FP + cc * 16) =
                *(const uint4*)(g_wt_hi + (size_t)n * FF + kc * 128 + cc * 8);
            *(uint4*)(pWl + n * FP + cc * 16) =
                *(const uint4*)(g_wt_lo + (size_t)n * FF + kc * 128 + cc * 8);
        }
        __syncthreads();

        #pragma unroll
        for (int term = 0; term < 3; term++) {
            const uint32_t Ab = (term == 2) ? sAl : sAh;
            const uint32_t Wb = (term == 1) ? sWl : sWh;
            const uint32_t aoff = Ab + (m0 + a_row) * FP + a_half * 16;
            const uint32_t boff = Wb + (n0 + b_row) * FP + b_half * 16;
            #pragma unroll
            for (int ks = 0; ks < 8; ks++) {
                const uint32_t kb = ks * 32;
                uint32_t af[4][4];
                #pragma unroll
                for (int mi = 0; mi < 4; mi++)
                    ldsm4(af[mi][0], af[mi][1], af[mi][2], af[mi][3],
                          aoff + mi * (16 * FP) + kb);
                uint32_t bf[3][4];
                #pragma unroll
                for (int pr = 0; pr < 3; pr++)
                    ldsm4(bf[pr][0], bf[pr][1], bf[pr][2], bf[pr][3],
                          boff + pr * (16 * FP) + kb);
                #pragma unroll
                for (int mi = 0; mi < 4; mi++)
                    #pragma unroll
                    for (int nj = 0; nj < 5; nj++)
                        mma_bf16(acc[mi][nj], af[mi],
                                 bf[nj >> 1][2 * (nj & 1)], bf[nj >> 1][2 * (nj & 1) + 1]);
            }
        }
        __syncthreads();
    }

    float zg = gen_number[b] * W_gen[0] + b_gen[0];
    const float gen = zg > 0.0f ? zg : 0.01f * zg;
    if (tid < NO) {
        sbias[tid] = (tid < HA)
            ? gen * W_act[(size_t)FF * HA + tid] + b_act[tid]
            : gen * W_v1[(size_t)FF * HV + (tid - HA)] + b_v1[tid - HA];
    }
    if (tid < HV) sv2[tid] = W_v2[tid];

    float* sh = (float*)sm;
    #pragma unroll
    for (int mi = 0; mi < 4; mi++)
        #pragma unroll
        for (int nj = 0; nj < 5; nj++) {
            int r = m0 + mi * 16 + (lane >> 2);
            int c = n0 + nj * 8 + 2 * (lane & 3);
            sh[r * HP + c]           = acc[mi][nj][0];
            sh[r * HP + c + 1]       = acc[mi][nj][1];
            sh[(r + 8) * HP + c]     = acc[mi][nj][2];
            sh[(r + 8) * HP + c + 1] = acc[mi][nj][3];
        }
    __syncthreads();

    if (tid < 128) {
        const int r = tid;
        float ss = 0.0f;
        #pragma unroll 8
        for (int c = 0; c < HA; c++) {
            float x = sh[r * HP + c] + sbias[c];
            ss += x * x;
        }
        snorm[r] = 1.0f / fmaxf(sqrtf(ss), 1e-8f);
        float vsum = 0.0f;
        #pragma unroll
        for (int j = 0; j < HV; j++) {
            float x = sh[r * HP + HA + j] + sbias[HA + j];
            vsum += fmaxf(x, 0.0f) * sv2[j];
        }
        srowv[r] = vsum;
    }
    __syncthreads();

    #pragma unroll
    for (int it = 0; it < 16; it++) {
        int u = tid + it * 256;
        int r = u >> 5, c4 = (u & 31) * 4;
        float rn = snorm[r];
        float x0 = (sh[r * HP + c4 + 0] + sbias[c4 + 0]) * rn;
        float x1 = (sh[r * HP + c4 + 1] + sbias[c4 + 1]) * rn;
        float x2 = (sh[r * HP + c4 + 2] + sbias[c4 + 2]) * rn;
        float x3 = (sh[r * HP + c4 + 3] + sbias[c4 + 3]) * rn;
        __nv_bfloat16 h0 = __float2bfloat16(x0), h1 = __float2bfloat16(x1);
        __nv_bfloat16 h2 = __float2bfloat16(x2), h3 = __float2bfloat16(x3);
        size_t o = (size_t)(g0 + r) * HA + c4;
        *(__nv_bfloat162*)(g_hi + o)     = __nv_bfloat162(h0, h1);
        *(__nv_bfloat162*)(g_hi + o + 2) = __nv_bfloat162(h2, h3);
        *(__nv_bfloat162*)(g_lo + o) =
            __nv_bfloat162(__float2bfloat16(x0 - __bfloat162float(h0)),
                           __float2bfloat16(x1 - __bfloat162float(h1)));
        *(__nv_bfloat162*)(g_lo + o + 2) =
            __nv_bfloat162(__float2bfloat16(x2 - __bfloat162float(h2)),
                           __float2bfloat16(x3 - __bfloat162float(h3)));
    }

    if (tid < 32) {
        float s = srowv[tid] + srowv[tid + 32] + srowv[tid + 64] + srowv[tid + 96];
        #pragma unroll
        for (int o = 16; o > 0; o >>= 1) s += __shfl_xor_sync(0xffffffffu, s, o);
        if (tid == 0) g_critpart[blockIdx.x] = s;
    }
}

// ================= kernel 2: actor = -hn @ hn^T (persistent, pipelined) ======
// Fragment-level software pipeline: 12 ldsm.x4 per k-step (Ah/Al/Bh/Bl shared
// across the 3 split terms), double-buffered in registers so ks+1 loads overlap
// the 48 MMAs of ks.
#define TPITCH 272
#define TBYTES (128 * TPITCH)            // 34816 per tile
#define PAIRB  (2 * TBYTES)              // hi+lo pair
#define ACTOR_SMEM (PAIRB + 2 * PAIRB)   // A pair + 2 B buffers = 208896
#define NWORK (BB * 528)                 // 2112
#define NCTA 148

struct Frags {
    uint32_t ah[4][4];
    uint32_t al[4][4];
    uint32_t bh[2][4];
    uint32_t bl[2][4];
};

__device__ __forceinline__ void load_frags(Frags& f, uint32_t aoh, uint32_t aol,
                                           uint32_t boh, uint32_t bol, uint32_t kb) {
    #pragma unroll
    for (int mi = 0; mi < 4; mi++)
        ldsm4(f.ah[mi][0], f.ah[mi][1], f.ah[mi][2], f.ah[mi][3],
              aoh + mi * (16 * TPITCH) + kb);
    #pragma unroll
    for (int pr = 0; pr < 2; pr++)
        ldsm4(f.bh[pr][0], f.bh[pr][1], f.bh[pr][2], f.bh[pr][3],
              boh + pr * (16 * TPITCH) + kb);
    #pragma unroll
    for (int mi = 0; mi < 4; mi++)
        ldsm4(f.al[mi][0], f.al[mi][1], f.al[mi][2], f.al[mi][3],
              aol + mi * (16 * TPITCH) + kb);
    #pragma unroll
    for (int pr = 0; pr < 2; pr++)
        ldsm4(f.bl[pr][0], f.bl[pr][1], f.bl[pr][2], f.bl[pr][3],
              bol + pr * (16 * TPITCH) + kb);
}

__device__ __forceinline__ void mma_step(float acc[4][4][4], const Frags& f) {
    // term 0: Ah * Bh
    #pragma unroll
    for (int mi = 0; mi < 4; mi++)
        #pragma unroll
        for (int nj = 0; nj < 4; nj++)
            mma_bf16(acc[mi][nj], f.ah[mi],
                     f.bh[nj >> 1][2 * (nj & 1)], f.bh[nj >> 1][2 * (nj & 1) + 1]);
    // term 1: Ah * Bl
    #pragma unroll
    for (int mi = 0; mi < 4; mi++)
        #pragma unroll
        for (int nj = 0; nj < 4; nj++)
            mma_bf16(acc[mi][nj], f.ah[mi],
                     f.bl[nj >> 1][2 * (nj & 1)], f.bl[nj >> 1][2 * (nj & 1) + 1]);
    // term 2: Al * Bh
    #pragma unroll
    for (int mi = 0; mi < 4; mi++)
        #pragma unroll
        for (int nj = 0; nj < 4; nj++)
            mma_bf16(acc[mi][nj], f.al[mi],
                     f.bh[nj >> 1][2 * (nj & 1)], f.bh[nj >> 1][2 * (nj & 1) + 1]);
}

__device__ __forceinline__ void issue_pair(char* dst, int b_, int tile, int tid) {
    const size_t rowbase = ((size_t)b_ * NN + (size_t)tile * 128) * HA;
    #pragma unroll
    for (int it = 0; it < 8; it++) {
        int u = tid + it * 256;
        int r = u >> 4, cc = u & 15;
        cp16(smem_u32(dst + r * TPITCH + cc * 16),
             (const char*)(g_hi + rowbase + (size_t)r * HA) + cc * 16);
        cp16(smem_u32(dst + TBYTES + r * TPITCH + cc * 16),
             (const char*)(g_lo + rowbase + (size_t)r * HA) + cc * 16);
    }
}

__global__ void __launch_bounds__(256, 1)
actor_gemm_mma(float* __restrict__ out) {
    extern __shared__ char sm[];
    const int tid = threadIdx.x;
    const int wid = tid >> 5, lane = tid & 31;

    const int start = (int)((long long)blockIdx.x * NWORK / NCTA);
    const int end   = (int)((long long)(blockIdx.x + 1) * NWORK / NCTA);

    int b = start / 528;
    int t = start - b * 528;
    int bi = 0;
    while (t >= 32 - bi) { t -= 32 - bi; bi++; }
    int bj = bi + t;

    char* pA  = sm;
    char* pB0 = sm + PAIRB;
    char* pB1 = sm + 2 * PAIRB;

    issue_pair(pA, b, bi, tid);  CP_COMMIT;
    issue_pair((start & 1) ? pB1 : pB0, b, bj, tid);  CP_COMMIT;
    bool need_A = false;

    const int wm = wid & 1, wn = wid >> 1;
    const int m0 = wm * 64, n0 = wn * 32;
    const int a_row  = lane & 15;
    const int a_half = lane >> 4;
    const int b_row  = ((lane >> 4) << 3) + (lane & 7);
    const int b_half = (lane >> 3) & 1;
    const size_t NSQ = (size_t)NN * NN;

    for (int s = start; s < end; s++) {
        char* pB = (s & 1) ? pB1 : pB0;

        int nb = b, nbi = bi, nbj = bj + 1;
        const bool have_next = (s + 1 < end);
        if (have_next && nbj == 32) {
            nbi++;
            if (nbi == 32) { nb++; nbi = 0; }
            nbj = nbi;
        }
        const bool next_newA = have_next && (nbi != bi || nb != b);

        if (need_A) { issue_pair(pA, b, bi, tid); CP_COMMIT; }
        bool prefetched = false;
        if (have_next) {
            issue_pair(((s + 1) & 1) ? pB1 : pB0, nb, nbj, tid);
            CP_COMMIT;
            prefetched = true;
        }
        if (prefetched) CP_WAIT1; else CP_WAIT0;
        __syncthreads();

        const uint32_t sA = smem_u32(pA);
        const uint32_t sB = smem_u32(pB);
        const uint32_t aoh = sA + (m0 + a_row) * TPITCH + a_half * 16;
        const uint32_t aol = aoh + TBYTES;
        const uint32_t boh = sB + (n0 + b_row) * TPITCH + b_half * 16;
        const uint32_t bol = boh + TBYTES;

        float acc[4][4][4];
        #pragma unroll
        for (int mi = 0; mi < 4; mi++)
            #pragma unroll
            for (int nj = 0; nj < 4; nj++)
                #pragma unroll
                for (int q = 0; q < 4; q++) acc[mi][nj][q] = 0.0f;

        // software-pipelined k-loop: frag double buffer in registers
        Frags fr[2];
        load_frags(fr[0], aoh, aol, boh, bol, 0);
        #pragma unroll
        for (int ks = 0; ks < 8; ks++) {
            if (ks < 7)
                load_frags(fr[(ks + 1) & 1], aoh, aol, boh, bol, (ks + 1) * 32);
            mma_step(acc, fr[ks & 1]);
        }

        // ---- epilogue: negate + direct stores (+ mirrored tile for bi != bj)
        float* ob = out + (size_t)b * NSQ;
        const int rbase = bi * 128 + m0 + (lane >> 2);
        const int cbase = bj * 128 + n0 + 2 * (lane & 3);
        #pragma unroll
        for (int mi = 0; mi < 4; mi++) {
            #pragma unroll
            for (int nj = 0; nj < 4; nj++) {
                float v0 = -acc[mi][nj][0], v1 = -acc[mi][nj][1];
                float v2 = -acc[mi][nj][2], v3 = -acc[mi][nj][3];
                const int r0 = rbase + mi * 16;
                const int c0 = cbase + nj * 8;
                *(float2*)(ob + (size_t)r0 * NN + c0)       = make_float2(v0, v1);
                *(float2*)(ob + (size_t)(r0 + 8) * NN + c0) = make_float2(v2, v3);
                if (bi != bj) {
                    ob[(size_t)c0 * NN + r0]           = v0;
                    ob[(size_t)(c0 + 1) * NN + r0]     = v1;
                    ob[(size_t)c0 * NN + r0 + 8]       = v2;
                    ob[(size_t)(c0 + 1) * NN + r0 + 8] = v3;
                }
            }
        }
        __syncthreads();

        b = nb; bi = nbi; bj = nbj;
        need_A = next_newA;
    }
}

// ================= kernel 3: deterministic critic reduction ==================
__global__ void critic_finish(float* __restrict__ out,
                              const float* __restrict__ b_v2,
                              size_t critic_base) {
    const int b = blockIdx.x, tid = threadIdx.x;
    float s = g_critpart[b * 32 + tid];
    #pragma unroll
    for (int o = 16; o > 0; o >>= 1) s += __shfl_xor_sync(0xffffffffu, s, o);
    if (tid == 0) out[critic_base + b] = s / (float)NN + b_v2[0];
}

// ================= launch =====================================================
extern "C" void kernel_launch(void* const* d_in, const int* in_sizes, int n_in,
                              void* d_out, int out_size) {
    const float* obs        = (const float*)d_in[0];
    const float* gen_number = (const float*)d_in[1];
    const float* W_gen      = (const float*)d_in[2];
    const float* b_gen      = (const float*)d_in[3];
    const float* W_act      = (const float*)d_in[4];
    const float* b_act      = (const float*)d_in[5];
    const float* W_v1       = (const float*)d_in[6];
    const float* b_v1       = (const float*)d_in[7];
    const float* W_v2       = (const float*)d_in[8];
    const float* b_v2       = (const float*)d_in[9];
    float* out = (float*)d_out;

    cudaFuncSetAttribute(feat_kernel,
                         cudaFuncAttributeMaxDynamicSharedMemorySize, FEAT_SMEM);
    cudaFuncSetAttribute(actor_gemm_mma,
                         cudaFuncAttributeMaxDynamicSharedMemorySize, ACTOR_SMEM);

    wsplit_kernel<<<(NO * FF + 255) / 256, 256>>>(W_act, W_v1);
    feat_kernel<<<128, 256, FEAT_SMEM>>>(obs, gen_number, W_gen, b_gen,
                                         W_act, b_act, W_v1, b_v1, W_v2);
    actor_gemm_mma<<<NCTA, 256, ACTOR_SMEM>>>(out);
    critic_finish<<<BB, 32>>>(out, b_v2, (size_t)out_size - BB);
}